// round 14
// baseline (speedup 1.0000x reference)
#include <cuda_runtime.h>

#define N_NODES 4096
#define T_STEPS 48
#define IN_DIM  2
#define H_DIM   64
#define H4      256
#define P_DIM   12
#define MAXW    160      // max nnz/row (mean ~42, huge margin)
#define NBW     128      // worker blocks (32 rows each)
#define NBT     148      // total blocks incl. barrier spinners
#define SR      36       // smem row stride (floats), 16B-aligned quads

typedef unsigned long long ull;

// ---------------- device scratch (static, allocation-free) ----------------
__device__ float g_dinv[N_NODES];
__device__ int   g_nnz[N_NODES];
__device__ int   g_cols[N_NODES * MAXW];
__device__ float g_vals[N_NODES * MAXW];
// interleaved hidden state: [buf][node][0:64)=h0, [64:128)=h1
__device__ float g_hh[2][N_NODES * 128];
__device__ float g_xT[N_NODES * T_STEPS * IN_DIM];   // [j][t][k]
__device__ float g_AX[T_STEPS * N_NODES * IN_DIM];   // [t][i][k]
__device__ float g_Wg0[66 * H4];
__device__ float g_Wl0[66 * H4];
__device__ float g_b0[H4];
__device__ float g_Wg1[128 * H4];
__device__ float g_Wl1[128 * H4];
__device__ float g_b1[H4];
__device__ unsigned g_cnt;
__device__ volatile unsigned g_gen;

// ---------------- packed fp32x2 helpers ----------------
__device__ __forceinline__ ull pack2(float a, float b) {
    ull r; asm("mov.b64 %0, {%1, %2};" : "=l"(r) : "f"(a), "f"(b)); return r;
}
__device__ __forceinline__ void unpack2(ull v, float& lo, float& hi) {
    asm("mov.b64 {%0, %1}, %2;" : "=f"(lo), "=f"(hi) : "l"(v));
}
__device__ __forceinline__ void fma2(ull& d, ull a, ull b) {
    asm("fma.rn.f32x2 %0, %1, %2, %0;" : "+l"(d) : "l"(a), "l"(b));
}
__device__ __forceinline__ float sigmoidf_(float x) {
    return 1.0f / (1.0f + __expf(-x));
}

// ---------------- grid barrier ----------------
__device__ __forceinline__ void gridbar() {
    __threadfence();
    __syncthreads();
    if (threadIdx.x == 0) {
        unsigned g = g_gen;
        if (atomicAdd(&g_cnt, 1u) == NBT - 1) {
            g_cnt = 0u;
            __threadfence();
            g_gen = g + 1u;
        } else {
            while (g_gen == g) __nanosleep(64);
        }
        __threadfence();
    }
    __syncthreads();
}

// ---------------- preprocessing ----------------
__global__ void rowsum_kernel(const float* __restrict__ adj) {
    int i = blockIdx.x;
    const float* row = adj + (size_t)i * N_NODES;
    float s = 0.f;
    for (int j = threadIdx.x; j < N_NODES; j += 256) s += row[j];
    #pragma unroll
    for (int o = 16; o > 0; o >>= 1) s += __shfl_xor_sync(0xffffffffu, s, o);
    __shared__ float red[8];
    if ((threadIdx.x & 31) == 0) red[threadIdx.x >> 5] = s;
    __syncthreads();
    if (threadIdx.x == 0) {
        float t = 0.f;
        for (int w = 0; w < 8; w++) t += red[w];
        g_dinv[i] = rsqrtf(t + 1.0f);
    }
}

// deterministic padded-CSR build (block prefix scan, no atomics)
__global__ void build_sparse(const float* __restrict__ adj) {
    int i = blockIdx.x;
    int tid = threadIdx.x;  // 256
    __shared__ int sc[256];
    int   locj[16];
    float locv[16];
    int lc = 0;
    int jbase = tid * 16;
    const float* row = adj + (size_t)i * N_NODES;
    #pragma unroll
    for (int jj = 0; jj < 16; jj++) {
        int j = jbase + jj;
        float a = row[j];
        bool dg = (j == i);
        if (a != 0.f || dg) { locj[lc] = j; locv[lc] = a + (dg ? 1.f : 0.f); lc++; }
    }
    sc[tid] = lc;
    __syncthreads();
    for (int off = 1; off < 256; off <<= 1) {
        int v = (tid >= off) ? sc[tid - off] : 0;
        __syncthreads();
        sc[tid] += v;
        __syncthreads();
    }
    int start = sc[tid] - lc;
    float di = g_dinv[i];
    for (int u = 0; u < lc; u++) {
        int p = start + u;
        if (p < MAXW) {
            int j = locj[u];
            g_cols[i * MAXW + p] = j;
            g_vals[i * MAXW + p] = locv[u] * di * g_dinv[j];
        }
    }
    if (tid == 255) g_nnz[i] = min(sc[255], MAXW);
}

__global__ void prep_weights(
    const float* __restrict__ gcWi0, const float* __restrict__ gcbi0,
    const float* __restrict__ gcWh0, const float* __restrict__ gcbh0,
    const float* __restrict__ liWi0, const float* __restrict__ libi0,
    const float* __restrict__ liWh0, const float* __restrict__ libh0,
    const float* __restrict__ gcWi1, const float* __restrict__ gcbi1,
    const float* __restrict__ gcWh1, const float* __restrict__ gcbh1,
    const float* __restrict__ liWi1, const float* __restrict__ libi1,
    const float* __restrict__ liWh1, const float* __restrict__ libh1) {
    int c = threadIdx.x;  // 256 threads, 1 block
    for (int r = 0; r < 2;  r++) g_Wg0[r * H4 + c]        = gcWi0[r * H4 + c];
    for (int r = 0; r < 64; r++) g_Wg0[(r + 2) * H4 + c]  = gcWh0[r * H4 + c];
    for (int r = 0; r < 2;  r++) g_Wl0[r * H4 + c]        = liWi0[r * H4 + c];
    for (int r = 0; r < 64; r++) g_Wl0[(r + 2) * H4 + c]  = liWh0[r * H4 + c];
    for (int r = 0; r < 64; r++) g_Wg1[r * H4 + c]        = gcWi1[r * H4 + c];
    for (int r = 0; r < 64; r++) g_Wg1[(r + 64) * H4 + c] = gcWh1[r * H4 + c];
    for (int r = 0; r < 64; r++) g_Wl1[r * H4 + c]        = liWi1[r * H4 + c];
    for (int r = 0; r < 64; r++) g_Wl1[(r + 64) * H4 + c] = liWh1[r * H4 + c];
    g_b0[c] = gcbi0[c] + gcbh0[c] + libi0[c] + libh0[c];
    g_b1[c] = gcbi1[c] + gcbh1[c] + libi1[c] + libh1[c];
}

// x[t][j][k] -> xT[j][t][k]
__global__ void xpose_kernel(const float* __restrict__ x) {
    int idx = blockIdx.x * 256 + threadIdx.x;
    if (idx < T_STEPS * N_NODES * IN_DIM) {
        int t = idx / (N_NODES * IN_DIM);
        int rem = idx - t * (N_NODES * IN_DIM);
        int j = rem >> 1, k = rem & 1;
        g_xT[j * (T_STEPS * IN_DIM) + t * IN_DIM + k] = x[idx];
    }
}

// AX[t][i][k] = sum_e v * xT[j][t][k]
__global__ void __launch_bounds__(128) ax_kernel() {
    __shared__ int   ec[MAXW];
    __shared__ float ev[MAXW];
    int i = blockIdx.x;
    int tid = threadIdx.x;
    int nnz = g_nnz[i];
    for (int e = tid; e < nnz; e += 128) {
        ec[e] = g_cols[i * MAXW + e];
        ev[e] = g_vals[i * MAXW + e];
    }
    __syncthreads();
    if (tid < T_STEPS * IN_DIM) {
        float a0 = 0.f, a1 = 0.f, a2 = 0.f, a3 = 0.f;
        int e = 0;
        for (; e + 4 <= nnz; e += 4) {
            a0 += ev[e]     * g_xT[(size_t)ec[e]     * 96 + tid];
            a1 += ev[e + 1] * g_xT[(size_t)ec[e + 1] * 96 + tid];
            a2 += ev[e + 2] * g_xT[(size_t)ec[e + 2] * 96 + tid];
            a3 += ev[e + 3] * g_xT[(size_t)ec[e + 3] * 96 + tid];
        }
        for (; e < nnz; e++) a0 += ev[e] * g_xT[(size_t)ec[e] * 96 + tid];
        int t = tid >> 1, k = tid & 1;
        g_AX[(size_t)t * (N_NODES * IN_DIM) + i * IN_DIM + k] = (a0 + a1) + (a2 + a3);
    }
}

__global__ void init_state() {
    int idx = blockIdx.x * blockDim.x + threadIdx.x;
    int tot = 2 * N_NODES * 128;
    if (idx < tot) ((float*)g_hh)[idx] = 0.f;
    if (idx == 0) { g_cnt = 0u; g_gen = 0u; }
}

// ---------------- fused GEMM + gates (32 rows, 512 threads) ----------------
// 8 row-groups x 64 threads; thread owns 4 cols (float4 weight loads) and
// 2 row-pairs (LDS.128 az/z quads). comb -> gates -> c (smem), h (smem T + g_hh).
template <int K>
__device__ __forceinline__ void cell_gemm(
    const float* azb, const float* zb,
    const float* __restrict__ Wg, const float* __restrict__ Wl,
    const float* __restrict__ bias,
    float* s_comb, float* s_cL, float* hT, float* __restrict__ hhG,
    int row0, int tid) {
    int g  = tid >> 6;          // row-group: rows 4g..4g+3
    int c0 = (tid & 63) << 2;   // 4 columns c0..c0+3

    ull acc[2][4];
    const ull zz = pack2(0.f, 0.f);
    #pragma unroll
    for (int rp = 0; rp < 2; rp++)
        #pragma unroll
        for (int c = 0; c < 4; c++) acc[rp][c] = zz;

    #pragma unroll 2
    for (int k = 0; k < K; k++) {
        float4 wg = __ldg(reinterpret_cast<const float4*>(Wg + k * H4 + c0));
        float4 wl = __ldg(reinterpret_cast<const float4*>(Wl + k * H4 + c0));
        ulonglong2 av = *reinterpret_cast<const ulonglong2*>(azb + k * SR + 4 * g);
        ulonglong2 zv = *reinterpret_cast<const ulonglong2*>(zb  + k * SR + 4 * g);
        ull w;
        w = pack2(wg.x, wg.x); fma2(acc[0][0], av.x, w); fma2(acc[1][0], av.y, w);
        w = pack2(wg.y, wg.y); fma2(acc[0][1], av.x, w); fma2(acc[1][1], av.y, w);
        w = pack2(wg.z, wg.z); fma2(acc[0][2], av.x, w); fma2(acc[1][2], av.y, w);
        w = pack2(wg.w, wg.w); fma2(acc[0][3], av.x, w); fma2(acc[1][3], av.y, w);
        w = pack2(wl.x, wl.x); fma2(acc[0][0], zv.x, w); fma2(acc[1][0], zv.y, w);
        w = pack2(wl.y, wl.y); fma2(acc[0][1], zv.x, w); fma2(acc[1][1], zv.y, w);
        w = pack2(wl.z, wl.z); fma2(acc[0][2], zv.x, w); fma2(acc[1][2], zv.y, w);
        w = pack2(wl.w, wl.w); fma2(acc[0][3], zv.x, w); fma2(acc[1][3], zv.y, w);
    }

    float4 bv = __ldg(reinterpret_cast<const float4*>(bias + c0));
    #pragma unroll
    for (int rp = 0; rp < 2; rp++) {
        int r = 4 * g + 2 * rp;
        float4 lo4, hi4;
        unpack2(acc[rp][0], lo4.x, hi4.x);
        unpack2(acc[rp][1], lo4.y, hi4.y);
        unpack2(acc[rp][2], lo4.z, hi4.z);
        unpack2(acc[rp][3], lo4.w, hi4.w);
        lo4.x += bv.x; lo4.y += bv.y; lo4.z += bv.z; lo4.w += bv.w;
        hi4.x += bv.x; hi4.y += bv.y; hi4.z += bv.z; hi4.w += bv.w;
        *reinterpret_cast<float4*>(s_comb + r * H4 + c0)       = lo4;
        *reinterpret_cast<float4*>(s_comb + (r + 1) * H4 + c0) = hi4;
    }
    __syncthreads();

    for (int u = tid; u < 32 * H_DIM; u += 512) {
        int r = u >> 6, hc = u & 63;
        const float* cb = s_comb + r * H4;
        float ig = cb[hc];
        float fg = cb[64 + hc];
        float og = cb[128 + hc];
        float gg = cb[192 + hc];
        float cold = s_cL[u];
        float nc = sigmoidf_(fg) * cold + sigmoidf_(ig) * tanhf(gg);
        float nh = sigmoidf_(og) * tanhf(nc);
        s_cL[u] = nc;
        hT[hc * SR + r] = nh;
        hhG[(size_t)(row0 + r) * 128 + hc] = nh;
    }
}

// ---------------- persistent kernel ----------------
// smem floats:
//  AZB  [0, 4680)        130 x 36 : r0-1 AX, 2-65 A@h0, 66-129 A@h1
//  ZB   [4680, 9360)     130 x 36 : r0-1 x_t, 2-65 h0T, 66-129 h1T
//  COMB [9360, 17552)    32 x 256
//  CST  [17552, 21648)   2 x 32 x 64
//  ECOL [21648, 26768)   32 x MAXW int
//  EVAL [26768, 31888)   32 x MAXW
//  NNZ  [31888, 31920)   32 int
#define SMEM_FLOATS 31920
#define SMEM_BYTES  (SMEM_FLOATS * 4)

__global__ void __launch_bounds__(512, 1) persist_kernel(
    const float* __restrict__ x,
    const float* __restrict__ outW,
    const float* __restrict__ outb,
    float* __restrict__ out) {
    extern __shared__ __align__(16) float sm[];
    float* s_azb  = sm;
    float* s_zb   = sm + 4680;
    float* s_comb = sm + 9360;
    float* s_c    = sm + 17552;
    int*   s_ecol = (int*)(sm + 21648);
    float* s_eval = sm + 26768;
    int*   s_nnz  = (int*)(sm + 31888);

    int tid = threadIdx.x;
    int w = tid >> 5, lane = tid & 31;
    int bid = blockIdx.x;

    if (bid >= NBW) {               // spinner blocks keep the barrier honest
        for (int s = 0; s < T_STEPS; s++) gridbar();
        return;
    }
    int row0 = bid * 32;

    // one-time init: zero az/z/c, stage edge lists
    for (int u = tid; u < 9360; u += 512) sm[u] = 0.f;
    for (int u = tid; u < 4096; u += 512) s_c[u] = 0.f;
    for (int u = tid; u < 32 * MAXW; u += 512) {
        int r = u / MAXW, e = u - r * MAXW;
        s_ecol[u] = g_cols[(row0 + r) * MAXW + e];
        s_eval[u] = g_vals[(row0 + r) * MAXW + e];
    }
    if (tid < 32) s_nnz[tid] = g_nnz[row0 + tid];
    __syncthreads();

    for (int t = 0; t < T_STEPS; t++) {
        const float* x_t = x + (size_t)t * N_NODES * IN_DIM;
        float* hh_cur = g_hh[t & 1];          // gather source this step
        float* hh_nxt = g_hh[(t + 1) & 1];    // cell1's h1 destination

        // ---- phase 1: stage x_t/AX rows 0-1, run cell0 (no gathers) ----
        for (int u = tid; u < 64; u += 512) {
            int r = u >> 1, k = u & 1;
            s_zb[k * SR + r]  = x_t[(row0 + r) * IN_DIM + k];
            s_azb[k * SR + r] = g_AX[(size_t)t * (N_NODES * IN_DIM) + (row0 + r) * IN_DIM + k];
        }
        __syncthreads();
        // cell0 writes h0(t) -> hh_cur cols [0:64)
        cell_gemm<66>(s_azb, s_zb, g_Wg0, g_Wl0, g_b0,
                      s_comb, s_c, s_zb + 2 * SR, hh_cur, row0, tid);

        gridbar();   // all h0(t) visible; h1(t-1) already in hh_cur cols [64:128)

        // ---- phase 2: one float4 gather pass over hh_cur, then cell1 ----
        for (int rr = 0; rr < 2; rr++) {
            int r = 2 * w + rr;
            int nnz = s_nnz[r];
            const int*   ec = s_ecol + r * MAXW;
            const float* ev = s_eval + r * MAXW;
            float ax = 0.f, ay = 0.f, az2 = 0.f, aw = 0.f;
            int e = 0;
            for (; e + 8 <= nnz; e += 8) {
                float4 hv[8]; float vv[8];
                #pragma unroll
                for (int u2 = 0; u2 < 8; u2++) {
                    int j = ec[e + u2];
                    vv[u2] = ev[e + u2];
                    hv[u2] = __ldg(reinterpret_cast<const float4*>(
                                 hh_cur + (size_t)j * 128) + lane);
                }
                #pragma unroll
                for (int u2 = 0; u2 < 8; u2++) {
                    ax += vv[u2] * hv[u2].x; ay += vv[u2] * hv[u2].y;
                    az2 += vv[u2] * hv[u2].z; aw += vv[u2] * hv[u2].w;
                }
            }
            for (; e < nnz; e++) {
                int j = ec[e]; float v = ev[e];
                float4 hv = __ldg(reinterpret_cast<const float4*>(
                                hh_cur + (size_t)j * 128) + lane);
                ax += v * hv.x; ay += v * hv.y; az2 += v * hv.z; aw += v * hv.w;
            }
            // lane covers h-cols 4*lane..4*lane+3 -> az rows 2+4*lane..+3
            int kr = 2 + 4 * lane;
            s_azb[(kr + 0) * SR + r] = ax;
            s_azb[(kr + 1) * SR + r] = ay;
            s_azb[(kr + 2) * SR + r] = az2;
            s_azb[(kr + 3) * SR + r] = aw;
        }
        __syncthreads();
        // cell1 writes h1(t) -> hh_nxt cols [64:128)
        cell_gemm<128>(s_azb + 2 * SR, s_zb + 2 * SR, g_Wg1, g_Wl1, g_b1,
                       s_comb, s_c + 2048, s_zb + 66 * SR, hh_nxt + 64, row0, tid);
    }
    __syncthreads();

    // ---- output: out = h1 @ outW + outb, h1 from smem h1T ----
    for (int u = tid; u < 32 * P_DIM; u += 512) {
        int r = u / P_DIM, p = u - r * P_DIM;
        float acc = outb[p];
        #pragma unroll
        for (int c2 = 0; c2 < H_DIM; c2++)
            acc += s_zb[(66 + c2) * SR + r] * __ldg(&outW[c2 * P_DIM + p]);
        out[(size_t)(row0 + r) * P_DIM + p] = acc;
    }
}

// ---------------- launch ----------------
extern "C" void kernel_launch(void* const* d_in, const int* in_sizes, int n_in,
                              void* d_out, int out_size) {
    const float* x     = (const float*)d_in[0];
    const float* adj   = (const float*)d_in[1];
    const float* gcWi0 = (const float*)d_in[2];
    const float* gcbi0 = (const float*)d_in[3];
    const float* gcWh0 = (const float*)d_in[4];
    const float* gcbh0 = (const float*)d_in[5];
    const float* liWi0 = (const float*)d_in[6];
    const float* libi0 = (const float*)d_in[7];
    const float* liWh0 = (const float*)d_in[8];
    const float* libh0 = (const float*)d_in[9];
    const float* gcWi1 = (const float*)d_in[10];
    const float* gcbi1 = (const float*)d_in[11];
    const float* gcWh1 = (const float*)d_in[12];
    const float* gcbh1 = (const float*)d_in[13];
    const float* liWi1 = (const float*)d_in[14];
    const float* libi1 = (const float*)d_in[15];
    const float* liWh1 = (const float*)d_in[16];
    const float* libh1 = (const float*)d_in[17];
    const float* outW  = (const float*)d_in[18];
    const float* outb  = (const float*)d_in[19];

    static int smem_set = 0;
    if (!smem_set) {
        cudaFuncSetAttribute(persist_kernel,
                             cudaFuncAttributeMaxDynamicSharedMemorySize,
                             SMEM_BYTES);
        smem_set = 1;
    }

    rowsum_kernel<<<N_NODES, 256>>>(adj);
    build_sparse<<<N_NODES, 256>>>(adj);
    prep_weights<<<1, 256>>>(gcWi0, gcbi0, gcWh0, gcbh0, liWi0, libi0, liWh0, libh0,
                             gcWi1, gcbi1, gcWh1, gcbh1, liWi1, libi1, liWh1, libh1);
    xpose_kernel<<<(T_STEPS * N_NODES * IN_DIM + 255) / 256, 256>>>(x);
    ax_kernel<<<N_NODES, 128>>>();
    init_state<<<(2 * N_NODES * 128 + 255) / 256, 256>>>();
    persist_kernel<<<NBT, 512, SMEM_BYTES>>>(x, outW, outb, (float*)d_out);
}

// round 16
// speedup vs baseline: 1.4410x; 1.4410x over previous
#include <cuda_runtime.h>

#define N_NODES 4096
#define T_STEPS 48
#define IN_DIM  2
#define H_DIM   64
#define H4      256
#define P_DIM   12
#define MAXW    160      // max nnz/row (mean ~42, >18 sigma margin)
#define NBW     128      // worker blocks (32 rows each)
#define NBT     148      // total blocks incl. barrier spinners (full grid)
#define SR      36       // padded smem row stride (floats), 16B-aligned quads

typedef unsigned long long ull;

// ---------------- device scratch (static, allocation-free) ----------------
__device__ float g_dinv[N_NODES];
__device__ int   g_nnz[N_NODES];
__device__ int   g_cols[N_NODES * MAXW];
__device__ float g_vals[N_NODES * MAXW];
__device__ float g_h0[2][N_NODES * H_DIM];
__device__ float g_h1[2][N_NODES * H_DIM];
__device__ float g_xT[N_NODES * T_STEPS * IN_DIM];   // [j][t][k]
__device__ float g_AX[T_STEPS * N_NODES * IN_DIM];   // [t][i][k]
__device__ float g_Wg0[66 * H4];
__device__ float g_Wl0[66 * H4];
__device__ float g_b0[H4];
__device__ float g_Wg1[128 * H4];
__device__ float g_Wl1[128 * H4];
__device__ float g_b1[H4];
__device__ unsigned g_cnt;
__device__ volatile unsigned g_gen;

// ---------------- packed fp32x2 helpers ----------------
__device__ __forceinline__ ull pack2(float a, float b) {
    ull r; asm("mov.b64 %0, {%1, %2};" : "=l"(r) : "f"(a), "f"(b)); return r;
}
__device__ __forceinline__ void unpack2(ull v, float& lo, float& hi) {
    asm("mov.b64 {%0, %1}, %2;" : "=f"(lo), "=f"(hi) : "l"(v));
}
__device__ __forceinline__ void fma2(ull& d, ull a, ull b) {
    asm("fma.rn.f32x2 %0, %1, %2, %0;" : "+l"(d) : "l"(a), "l"(b));
}
__device__ __forceinline__ float sigmoidf_(float x) {
    return 1.0f / (1.0f + __expf(-x));
}

// ---------------- grid barrier (generation counter, 148 arrivals) --------
__device__ __forceinline__ void gridbar() {
    __threadfence();
    __syncthreads();
    if (threadIdx.x == 0) {
        unsigned g = g_gen;
        if (atomicAdd(&g_cnt, 1u) == NBT - 1) {
            g_cnt = 0u;
            __threadfence();
            g_gen = g + 1u;
        } else {
            while (g_gen == g) __nanosleep(64);
        }
        __threadfence();
    }
    __syncthreads();
}

// ---------------- preprocessing ----------------
__global__ void rowsum_kernel(const float* __restrict__ adj) {
    int i = blockIdx.x;
    const float* row = adj + (size_t)i * N_NODES;
    float s = 0.f;
    for (int j = threadIdx.x; j < N_NODES; j += 256) s += row[j];
    #pragma unroll
    for (int o = 16; o > 0; o >>= 1) s += __shfl_xor_sync(0xffffffffu, s, o);
    __shared__ float red[8];
    if ((threadIdx.x & 31) == 0) red[threadIdx.x >> 5] = s;
    __syncthreads();
    if (threadIdx.x == 0) {
        float t = 0.f;
        for (int w = 0; w < 8; w++) t += red[w];
        g_dinv[i] = rsqrtf(t + 1.0f);
    }
}

// deterministic padded-CSR build (block prefix scan, no atomics)
__global__ void build_sparse(const float* __restrict__ adj) {
    int i = blockIdx.x;
    int tid = threadIdx.x;  // 256
    __shared__ int sc[256];
    int   locj[16];
    float locv[16];
    int lc = 0;
    int jbase = tid * 16;
    const float* row = adj + (size_t)i * N_NODES;
    #pragma unroll
    for (int jj = 0; jj < 16; jj++) {
        int j = jbase + jj;
        float a = row[j];
        bool dg = (j == i);
        if (a != 0.f || dg) { locj[lc] = j; locv[lc] = a + (dg ? 1.f : 0.f); lc++; }
    }
    sc[tid] = lc;
    __syncthreads();
    for (int off = 1; off < 256; off <<= 1) {
        int v = (tid >= off) ? sc[tid - off] : 0;
        __syncthreads();
        sc[tid] += v;
        __syncthreads();
    }
    int start = sc[tid] - lc;
    float di = g_dinv[i];
    for (int u = 0; u < lc; u++) {
        int p = start + u;
        if (p < MAXW) {
            int j = locj[u];
            g_cols[i * MAXW + p] = j;
            g_vals[i * MAXW + p] = locv[u] * di * g_dinv[j];
        }
    }
    if (tid == 255) g_nnz[i] = min(sc[255], MAXW);
}

__global__ void prep_weights(
    const float* __restrict__ gcWi0, const float* __restrict__ gcbi0,
    const float* __restrict__ gcWh0, const float* __restrict__ gcbh0,
    const float* __restrict__ liWi0, const float* __restrict__ libi0,
    const float* __restrict__ liWh0, const float* __restrict__ libh0,
    const float* __restrict__ gcWi1, const float* __restrict__ gcbi1,
    const float* __restrict__ gcWh1, const float* __restrict__ gcbh1,
    const float* __restrict__ liWi1, const float* __restrict__ libi1,
    const float* __restrict__ liWh1, const float* __restrict__ libh1) {
    int c = threadIdx.x;  // 256 threads, 1 block
    for (int r = 0; r < 2;  r++) g_Wg0[r * H4 + c]        = gcWi0[r * H4 + c];
    for (int r = 0; r < 64; r++) g_Wg0[(r + 2) * H4 + c]  = gcWh0[r * H4 + c];
    for (int r = 0; r < 2;  r++) g_Wl0[r * H4 + c]        = liWi0[r * H4 + c];
    for (int r = 0; r < 64; r++) g_Wl0[(r + 2) * H4 + c]  = liWh0[r * H4 + c];
    for (int r = 0; r < 64; r++) g_Wg1[r * H4 + c]        = gcWi1[r * H4 + c];
    for (int r = 0; r < 64; r++) g_Wg1[(r + 64) * H4 + c] = gcWh1[r * H4 + c];
    for (int r = 0; r < 64; r++) g_Wl1[r * H4 + c]        = liWi1[r * H4 + c];
    for (int r = 0; r < 64; r++) g_Wl1[(r + 64) * H4 + c] = liWh1[r * H4 + c];
    g_b0[c] = gcbi0[c] + gcbh0[c] + libi0[c] + libh0[c];
    g_b1[c] = gcbi1[c] + gcbh1[c] + libi1[c] + libh1[c];
}

// x[t][j][k] -> xT[j][t][k]
__global__ void xpose_kernel(const float* __restrict__ x) {
    int idx = blockIdx.x * 256 + threadIdx.x;
    if (idx < T_STEPS * N_NODES * IN_DIM) {
        int t = idx / (N_NODES * IN_DIM);
        int rem = idx - t * (N_NODES * IN_DIM);
        int j = rem >> 1, k = rem & 1;
        g_xT[j * (T_STEPS * IN_DIM) + t * IN_DIM + k] = x[idx];
    }
}

// AX[t][i][k] = sum_e v * xT[j][t][k]
__global__ void __launch_bounds__(128) ax_kernel() {
    __shared__ int   ec[MAXW];
    __shared__ float ev[MAXW];
    int i = blockIdx.x;
    int tid = threadIdx.x;
    int nnz = g_nnz[i];
    for (int e = tid; e < nnz; e += 128) {
        ec[e] = g_cols[i * MAXW + e];
        ev[e] = g_vals[i * MAXW + e];
    }
    __syncthreads();
    if (tid < T_STEPS * IN_DIM) {
        float a0 = 0.f, a1 = 0.f, a2 = 0.f, a3 = 0.f;
        int e = 0;
        for (; e + 4 <= nnz; e += 4) {
            a0 += ev[e]     * g_xT[(size_t)ec[e]     * 96 + tid];
            a1 += ev[e + 1] * g_xT[(size_t)ec[e + 1] * 96 + tid];
            a2 += ev[e + 2] * g_xT[(size_t)ec[e + 2] * 96 + tid];
            a3 += ev[e + 3] * g_xT[(size_t)ec[e + 3] * 96 + tid];
        }
        for (; e < nnz; e++) a0 += ev[e] * g_xT[(size_t)ec[e] * 96 + tid];
        int t = tid >> 1, k = tid & 1;
        g_AX[(size_t)t * (N_NODES * IN_DIM) + i * IN_DIM + k] = (a0 + a1) + (a2 + a3);
    }
}

__global__ void init_state() {
    int idx = blockIdx.x * blockDim.x + threadIdx.x;
    if (idx < N_NODES * H_DIM) {
        g_h0[0][idx] = 0.f; g_h0[1][idx] = 0.f;
        g_h1[0][idx] = 0.f; g_h1[1][idx] = 0.f;
    }
    if (idx == 0) { g_cnt = 0u; g_gen = 0u; }
}

// ---------------- fused GEMM + gates (32 rows, 512 threads) ----------------
// NEW tiling: thread owns 1 column (tid & 255) x 16 rows (16 * (tid >> 8)).
// Per k: 2 LDG.32 weights (min col-redundancy), 8 broadcast LDS.128 quads,
// 16 FMA2 into 8 shared comb accumulators. Then gates -> c (smem), h (smem T + global).
template <int K>
__device__ __forceinline__ void cell_gemm(
    const float* azb, const float* zb,
    const float* __restrict__ Wg, const float* __restrict__ Wl,
    const float* __restrict__ bias,
    float* s_comb, float* s_cL, float* hT, float* __restrict__ hG,
    int row0, int tid) {
    int half = tid >> 8;            // rows 16*half .. 16*half+15
    int c    = tid & 255;
    int rbase = 16 * half;

    ull acc[8];
    const ull zz = pack2(0.f, 0.f);
    #pragma unroll
    for (int rp = 0; rp < 8; rp++) acc[rp] = zz;

    #pragma unroll 2
    for (int k = 0; k < K; k++) {
        float wg = __ldg(&Wg[k * H4 + c]);
        float wl = __ldg(&Wl[k * H4 + c]);
        ull wgp = pack2(wg, wg), wlp = pack2(wl, wl);
        const ulonglong2* a4 =
            reinterpret_cast<const ulonglong2*>(azb + k * SR + rbase);
        const ulonglong2* b4 =
            reinterpret_cast<const ulonglong2*>(zb  + k * SR + rbase);
        #pragma unroll
        for (int q = 0; q < 4; q++) {
            ulonglong2 av = a4[q];
            fma2(acc[2 * q],     av.x, wgp);
            fma2(acc[2 * q + 1], av.y, wgp);
        }
        #pragma unroll
        for (int q = 0; q < 4; q++) {
            ulonglong2 bv = b4[q];
            fma2(acc[2 * q],     bv.x, wlp);
            fma2(acc[2 * q + 1], bv.y, wlp);
        }
    }

    float b = __ldg(&bias[c]);
    #pragma unroll
    for (int rp = 0; rp < 8; rp++) {
        int r = rbase + 2 * rp;
        float lo, hi;
        unpack2(acc[rp], lo, hi);
        s_comb[r * H4 + c]       = lo + b;
        s_comb[(r + 1) * H4 + c] = hi + b;
    }
    __syncthreads();

    for (int u = tid; u < 32 * H_DIM; u += 512) {
        int r = u >> 6, hc = u & 63;
        const float* cb = s_comb + r * H4;
        float ig = cb[hc];
        float fg = cb[64 + hc];
        float og = cb[128 + hc];
        float gg = cb[192 + hc];
        float cold = s_cL[u];
        float nc = sigmoidf_(fg) * cold + sigmoidf_(ig) * tanhf(gg);
        float nh = sigmoidf_(og) * tanhf(nc);
        s_cL[u] = nc;
        hT[hc * SR + r] = nh;
        hG[(size_t)(row0 + r) * H_DIM + hc] = nh;
    }
}

// ---------------- persistent kernel ----------------
// smem floats:
//  AZB  [0, 4680)        130 x 36 : r0-1 AX, 2-65 A@h0, 66-129 A@h1
//  ZB   [4680, 9360)     130 x 36 : r0-1 x_t, 2-65 h0T, 66-129 h1T
//  COMB [9360, 17552)    32 x 256
//  CST  [17552, 21648)   2 x 32 x 64
//  ECOL [21648, 26768)   32 x MAXW int
//  EVAL [26768, 31888)   32 x MAXW
//  NNZ  [31888, 31920)   32 int
#define SMEM_FLOATS 31920
#define SMEM_BYTES  (SMEM_FLOATS * 4)

__global__ void __launch_bounds__(512, 1) persist_kernel(
    const float* __restrict__ x,
    const float* __restrict__ outW,
    const float* __restrict__ outb,
    float* __restrict__ out) {
    extern __shared__ __align__(16) float sm[];
    float* s_azb  = sm;
    float* s_zb   = sm + 4680;
    float* s_comb = sm + 9360;
    float* s_c    = sm + 17552;
    int*   s_ecol = (int*)(sm + 21648);
    float* s_eval = sm + 26768;
    int*   s_nnz  = (int*)(sm + 31888);

    int tid = threadIdx.x;
    int w = tid >> 5, lane = tid & 31;
    int bid = blockIdx.x;

    if (bid >= NBW) {               // spinner blocks keep the barrier honest
        for (int s = 0; s < T_STEPS; s++) gridbar();
        return;
    }
    int row0 = bid * 32;

    // one-time init: zero az/z/c, stage edge lists
    for (int u = tid; u < 9360; u += 512) sm[u] = 0.f;
    for (int u = tid; u < 4096; u += 512) s_c[u] = 0.f;
    for (int u = tid; u < 32 * MAXW; u += 512) {
        int r = u / MAXW, e = u - r * MAXW;
        s_ecol[u] = g_cols[(row0 + r) * MAXW + e];
        s_eval[u] = g_vals[(row0 + r) * MAXW + e];
    }
    if (tid < 32) s_nnz[tid] = g_nnz[row0 + tid];
    __syncthreads();

    for (int t = 0; t < T_STEPS; t++) {
        int pc = t & 1, p1 = pc ^ 1;
        const float* x_t = x + (size_t)t * N_NODES * IN_DIM;

        // ---- phase 1: stage x_t/AX rows 0-1, run cell0 (no gathers) ----
        for (int u = tid; u < 64; u += 512) {
            int r = u >> 1, k = u & 1;
            s_zb[k * SR + r]  = x_t[(row0 + r) * IN_DIM + k];
            s_azb[k * SR + r] = g_AX[(size_t)t * (N_NODES * IN_DIM) + (row0 + r) * IN_DIM + k];
        }
        __syncthreads();
        cell_gemm<66>(s_azb, s_zb, g_Wg0, g_Wl0, g_b0,
                      s_comb, s_c, s_zb + 2 * SR, g_h0[p1], row0, tid);

        gridbar();   // all blocks' h0n visible; h1c from t-1 also safe

        // ---- phase 2: single gather pass (h0n + h1c), then cell1 ----
        {
            const float* h0s = g_h0[p1];
            const float* h1s = g_h1[pc];
            for (int rr = 0; rr < 2; rr++) {
                int r = 2 * w + rr;
                int nnz = s_nnz[r];
                const int*   ec = s_ecol + r * MAXW;
                const float* ev = s_eval + r * MAXW;
                float a0 = 0.f, a1 = 0.f, b0 = 0.f, b1 = 0.f;
                int e = 0;
                for (; e + 8 <= nnz; e += 8) {
                    float2 hv[8], gv[8]; float vv[8];
                    #pragma unroll
                    for (int u2 = 0; u2 < 8; u2++) {
                        int j = ec[e + u2];
                        vv[u2] = ev[e + u2];
                        hv[u2] = __ldg(reinterpret_cast<const float2*>(
                                     h0s + (size_t)j * H_DIM) + lane);
                        gv[u2] = __ldg(reinterpret_cast<const float2*>(
                                     h1s + (size_t)j * H_DIM) + lane);
                    }
                    #pragma unroll
                    for (int u2 = 0; u2 < 8; u2++) {
                        a0 += vv[u2] * hv[u2].x; a1 += vv[u2] * hv[u2].y;
                        b0 += vv[u2] * gv[u2].x; b1 += vv[u2] * gv[u2].y;
                    }
                }
                for (; e < nnz; e++) {
                    int j = ec[e]; float v = ev[e];
                    float2 hv = __ldg(reinterpret_cast<const float2*>(
                                    h0s + (size_t)j * H_DIM) + lane);
                    float2 gv = __ldg(reinterpret_cast<const float2*>(
                                    h1s + (size_t)j * H_DIM) + lane);
                    a0 += v * hv.x; a1 += v * hv.y;
                    b0 += v * gv.x; b1 += v * gv.y;
                }
                // A@h0n -> rows 2..65 (feeds cell1 now AND next step's cell0)
                s_azb[(2 + 2 * lane) * SR + r]  = a0;
                s_azb[(3 + 2 * lane) * SR + r]  = a1;
                // A@h1c -> rows 66..129
                s_azb[(66 + 2 * lane) * SR + r] = b0;
                s_azb[(67 + 2 * lane) * SR + r] = b1;
            }
        }
        __syncthreads();
        cell_gemm<128>(s_azb + 2 * SR, s_zb + 2 * SR, g_Wg1, g_Wl1, g_b1,
                       s_comb, s_c + 2048, s_zb + 66 * SR, g_h1[p1], row0, tid);
        // no end-of-step barrier needed (double-buffer parity analysis)
    }
    __syncthreads();

    // ---- output: out = h1 @ outW + outb, h1 read from smem h1T ----
    for (int u = tid; u < 32 * P_DIM; u += 512) {
        int r = u / P_DIM, p = u - r * P_DIM;
        float acc = outb[p];
        #pragma unroll
        for (int c2 = 0; c2 < H_DIM; c2++)
            acc += s_zb[(66 + c2) * SR + r] * __ldg(&outW[c2 * P_DIM + p]);
        out[(size_t)(row0 + r) * P_DIM + p] = acc;
    }
}

// ---------------- launch ----------------
extern "C" void kernel_launch(void* const* d_in, const int* in_sizes, int n_in,
                              void* d_out, int out_size) {
    const float* x     = (const float*)d_in[0];
    const float* adj   = (const float*)d_in[1];
    const float* gcWi0 = (const float*)d_in[2];
    const float* gcbi0 = (const float*)d_in[3];
    const float* gcWh0 = (const float*)d_in[4];
    const float* gcbh0 = (const float*)d_in[5];
    const float* liWi0 = (const float*)d_in[6];
    const float* libi0 = (const float*)d_in[7];
    const float* liWh0 = (const float*)d_in[8];
    const float* libh0 = (const float*)d_in[9];
    const float* gcWi1 = (const float*)d_in[10];
    const float* gcbi1 = (const float*)d_in[11];
    const float* gcWh1 = (const float*)d_in[12];
    const float* gcbh1 = (const float*)d_in[13];
    const float* liWi1 = (const float*)d_in[14];
    const float* libi1 = (const float*)d_in[15];
    const float* liWh1 = (const float*)d_in[16];
    const float* libh1 = (const float*)d_in[17];
    const float* outW  = (const float*)d_in[18];
    const float* outb  = (const float*)d_in[19];

    static int smem_set = 0;
    if (!smem_set) {
        cudaFuncSetAttribute(persist_kernel,
                             cudaFuncAttributeMaxDynamicSharedMemorySize,
                             SMEM_BYTES);
        smem_set = 1;
    }

    rowsum_kernel<<<N_NODES, 256>>>(adj);
    build_sparse<<<N_NODES, 256>>>(adj);
    prep_weights<<<1, 256>>>(gcWi0, gcbi0, gcWh0, gcbh0, liWi0, libi0, liWh0, libh0,
                             gcWi1, gcbi1, gcWh1, gcbh1, liWi1, libi1, liWh1, libh1);
    xpose_kernel<<<(T_STEPS * N_NODES * IN_DIM + 255) / 256, 256>>>(x);
    ax_kernel<<<N_NODES, 128>>>();
    init_state<<<(N_NODES * H_DIM + 255) / 256, 256>>>();
    persist_kernel<<<NBT, 512, SMEM_BYTES>>>(x, outW, outb, (float*)d_out);
}